// round 11
// baseline (speedup 1.0000x reference)
#include <cuda_runtime.h>

#define BB   8
#define HH   384
#define WW   384
#define HW   (HH * WW)
#define CIN  8
#define OCH  18

// Padded pf scratch: border of 2 zeros on every side, per (b, c) plane.
#define PW   388
#define PWW  (PW * PW)
__device__ float g_pad[BB * 3 * PWW];     // 14.45 MB

// Weights in constant memory (constant port, off the L1tex path).
__constant__ float c_ow[OCH * CIN * 9];   // [o][ci][ky*3+kx]
__constant__ float c_ob[OCH];
__constant__ float c_dw[81];              // [o][c][k] (3,3,9)

#define TW   128    // tile width  (32 threads x * 4 px)
#define TH   8      // tile height
#define SWD  132    // 130 used (128 + 2 halo), padded to 132 (16B rows)
#define SHD  10

// ---------- prepad: pf -> zero-bordered g_pad ----------
__global__ __launch_bounds__(256)
void prepad_k(const float* __restrict__ pf) {
    int idx = blockIdx.x * 256 + threadIdx.x;          // over BB*3*PW*PW
    if (idx >= BB * 3 * PWW) return;
    int x  = idx % PW;
    int y  = (idx / PW) % PW;
    int pl = idx / PWW;                                // plane: b*3+c
    int gy = y - 2, gx = x - 2;
    float v = 0.f;
    if ((unsigned)gy < (unsigned)HH && (unsigned)gx < (unsigned)WW)
        v = __ldg(pf + (long)pl * HW + gy * WW + gx);
    g_pad[idx] = v;
}

// Bilinear sample from padded pf: NO predication, clamp reproduces zero-pad.
__device__ __forceinline__ void sample_px(const float* __restrict__ pp,
                                          float py, float px, int k,
                                          float& a0, float& a1, float& a2) {
    float pyp = fminf(fmaxf(py + 2.f, 0.f), 386.f);
    float pxp = fminf(fmaxf(px + 2.f, 0.f), 386.f);
    int y0 = __float2int_rd(pyp);
    int x0 = __float2int_rd(pxp);
    float wy = pyp - (float)y0;
    float wx = pxp - (float)x0;
    float iy = 1.f - wy, ix = 1.f - wx;
    float w00 = iy * ix, w01 = iy * wx, w10 = wy * ix, w11 = wy * wx;
    int i00 = y0 * PW + x0;
#pragma unroll
    for (int c = 0; c < 3; ++c) {
        const float* p = pp + c * PWW;
        float v00 = __ldg(p + i00);
        float v01 = __ldg(p + i00 + 1);
        float v10 = __ldg(p + i00 + PW);
        float v11 = __ldg(p + i00 + PW + 1);
        float s = fmaf(w00, v00, fmaf(w01, v01, fmaf(w10, v10, w11 * v11)));
        a0 = fmaf(c_dw[0 * 27 + c * 9 + k], s, a0);
        a1 = fmaf(c_dw[1 * 27 + c * 9 + k], s, a1);
        a2 = fmaf(c_dw[2 * 27 + c * 9 + k], s, a2);
    }
}

// One pass: conv for och [2*K0, 2*K0+2*NT) over 4 px, then sample taps [K0, K0+NT).
template<int K0, int NT>
__device__ __forceinline__ void pass(const float* __restrict__ s_x,
                                     int tx, int ty,
                                     const float* __restrict__ pp,
                                     int h, int wp,
                                     float* __restrict__ a0,
                                     float* __restrict__ a1,
                                     float* __restrict__ a2) {
    float acc[2 * NT][4];
#pragma unroll
    for (int j = 0; j < 2 * NT; ++j) {
        float bv = c_ob[2 * K0 + j];
#pragma unroll
        for (int px = 0; px < 4; ++px) acc[j][px] = bv;
    }

#pragma unroll
    for (int ci = 0; ci < CIN; ++ci) {
#pragma unroll
        for (int ky = 0; ky < 3; ++ky) {
            const float* rp = s_x + (ci * SHD + (ty + ky)) * SWD + 4 * tx;
            float4 qa = *reinterpret_cast<const float4*>(rp);      // v0..v3 (16B aligned)
            float2 qb = *reinterpret_cast<const float2*>(rp + 4);  // v4,v5
            float v[6] = {qa.x, qa.y, qa.z, qa.w, qb.x, qb.y};
#pragma unroll
            for (int j = 0; j < 2 * NT; ++j) {
                const int o = 2 * K0 + j;
                float w0 = c_ow[o * 72 + ci * 9 + ky * 3 + 0];
                float w1 = c_ow[o * 72 + ci * 9 + ky * 3 + 1];
                float w2 = c_ow[o * 72 + ci * 9 + ky * 3 + 2];
#pragma unroll
                for (int px = 0; px < 4; ++px)
                    acc[j][px] = fmaf(v[px], w0,
                                 fmaf(v[px + 1], w1,
                                 fmaf(v[px + 2], w2, acc[j][px])));
            }
        }
    }

#pragma unroll
    for (int t = 0; t < NT; ++t) {
        const int k   = K0 + t;
        const int kyi = k / 3, kxi = k % 3;
        const float by = (float)(kyi + h - 1);
#pragma unroll
        for (int px = 0; px < 4; ++px) {
            float py  = acc[2 * t][px]     + by;
            float pxx = acc[2 * t + 1][px] + (float)(kxi + wp + px - 1);
            sample_px(pp, py, pxx, k, a0[px], a1[px], a2[px]);
        }
    }
}

__global__ __launch_bounds__(256, 3)
void guided_cnn_fused(const float* __restrict__ pf,
                      const float* __restrict__ cf,
                      const float* __restrict__ mv,
                      float* __restrict__ out) {
    __shared__ float s_x[CIN * SHD * SWD];    // 42240 B

    const int tx  = threadIdx.x;              // 0..31 (4 px each)
    const int ty  = threadIdx.y;              // 0..7
    const int tid = ty * 32 + tx;
    const int b   = blockIdx.z;
    const int h0  = blockIdx.y * TH;
    const int w0  = blockIdx.x * TW;

    // stage input tile (8 ch, halo 1, rows padded to 132)
    for (int i = tid; i < CIN * SHD * SWD; i += 256) {
        int c  = i % SWD;
        int r  = (i / SWD) % SHD;
        int ch = i / (SWD * SHD);
        int gh = h0 - 1 + r;
        int gw = w0 - 1 + c;
        float v = 0.f;
        if (c < 130 && (unsigned)gh < (unsigned)HH && (unsigned)gw < (unsigned)WW) {
            const float* src;
            if (ch < 3)      src = pf + (((long)b * 3 + ch)     * HH + gh) * WW + gw;
            else if (ch < 6) src = cf + (((long)b * 3 + ch - 3) * HH + gh) * WW + gw;
            else             src = mv + (((long)b * 2 + ch - 6) * HH + gh) * WW + gw;
            v = __ldg(src);
        }
        s_x[i] = v;
    }
    __syncthreads();

    const int h  = h0 + ty;
    const int wp = w0 + 4 * tx;
    const float* pp = g_pad + (long)b * 3 * PWW;   // padded pf, 3 planes

    float a0[4] = {0, 0, 0, 0};
    float a1[4] = {0, 0, 0, 0};
    float a2[4] = {0, 0, 0, 0};

    pass<0, 3>(s_x, tx, ty, pp, h, wp, a0, a1, a2);   // och 0..5,  taps 0..2
    pass<3, 3>(s_x, tx, ty, pp, h, wp, a0, a1, a2);   // och 6..11, taps 3..5
    pass<6, 3>(s_x, tx, ty, pp, h, wp, a0, a1, a2);   // och 12..17, taps 6..8

    float* o0 = out + (((long)b * 3 + 0) * HH + h) * WW + wp;
    float* o1 = out + (((long)b * 3 + 1) * HH + h) * WW + wp;
    float* o2 = out + (((long)b * 3 + 2) * HH + h) * WW + wp;
    *reinterpret_cast<float4*>(o0) = make_float4(a0[0], a0[1], a0[2], a0[3]);
    *reinterpret_cast<float4*>(o1) = make_float4(a1[0], a1[1], a1[2], a1[3]);
    *reinterpret_cast<float4*>(o2) = make_float4(a2[0], a2[1], a2[2], a2[3]);
}

extern "C" void kernel_launch(void* const* d_in, const int* in_sizes, int n_in,
                              void* d_out, int out_size) {
    const float* pf = (const float*)d_in[0];
    const float* cf = (const float*)d_in[1];
    const float* mv = (const float*)d_in[2];
    const float* ow = (const float*)d_in[3];
    const float* ob = (const float*)d_in[4];
    const float* dw = (const float*)d_in[5];
    float* out = (float*)d_out;

    // Stage weights into __constant__ (async D2D memcpys are graph-capturable).
    cudaMemcpyToSymbolAsync(c_ow, ow, OCH * CIN * 9 * sizeof(float), 0,
                            cudaMemcpyDeviceToDevice, 0);
    cudaMemcpyToSymbolAsync(c_ob, ob, OCH * sizeof(float), 0,
                            cudaMemcpyDeviceToDevice, 0);
    cudaMemcpyToSymbolAsync(c_dw, dw, 81 * sizeof(float), 0,
                            cudaMemcpyDeviceToDevice, 0);

    // Build zero-bordered pf copy (ordered before the fused kernel, same stream).
    int npad = BB * 3 * PWW;
    prepad_k<<<(npad + 255) / 256, 256>>>(pf);

    dim3 blk(32, 8);
    dim3 grd(WW / TW, HH / TH, BB);   // 3 x 48 x 8 = 1152
    guided_cnn_fused<<<grd, blk>>>(pf, cf, mv, out);
}

// round 12
// speedup vs baseline: 1.0351x; 1.0351x over previous
#include <cuda_runtime.h>

#define BB   8
#define HH   384
#define WW   384
#define HW   (HH * WW)
#define CIN  8
#define OCH  18

// Weights in constant memory: reads use the constant port, not LDS/LDG.
__constant__ float c_ow[OCH * CIN * 9];   // [o][ci][ky*3+kx]
__constant__ float c_ob[OCH];
__constant__ float c_dw[81];              // [o][c][k] (3,3,9)

#define TW   128    // tile width  (32 threads x * 4 px)
#define TH   8      // tile height
#define SWD  132    // 130 used (128 + 2 halo), padded to 132 (16B rows)
#define SHD  10

// Bilinear sample of pf (3 ch, zero pad) + accumulate.
// Validity folded into the bilinear WEIGHTS; loads are unpredicated at
// clamped (always in-bounds) addresses of the original pf.
__device__ __forceinline__ void sample_px(const float* __restrict__ p0,
                                          float py, float px, int k,
                                          float& a0, float& a1, float& a2) {
    int y0 = __float2int_rd(py);
    int x0 = __float2int_rd(px);
    float wy = py - (float)y0;
    float wx = px - (float)x0;
    // row/col weight factors, zeroed when that row/col is out of bounds
    float ry0 = ((unsigned)y0       < (unsigned)HH) ? (1.f - wy) : 0.f;
    float ry1 = ((unsigned)(y0 + 1) < (unsigned)HH) ? wy         : 0.f;
    float rx0 = ((unsigned)x0       < (unsigned)WW) ? (1.f - wx) : 0.f;
    float rx1 = ((unsigned)(x0 + 1) < (unsigned)WW) ? wx         : 0.f;
    float w00 = ry0 * rx0, w01 = ry0 * rx1, w10 = ry1 * rx0, w11 = ry1 * rx1;
    // clamped in-bounds addresses (zero weight kills any wrong-value term)
    int yc0 = min(max(y0, 0), HH - 1);
    int yc1 = min(max(y0 + 1, 0), HH - 1);
    int xc0 = min(max(x0, 0), WW - 1);
    int xc1 = min(max(x0 + 1, 0), WW - 1);
    int r0 = yc0 * WW, r1 = yc1 * WW;
#pragma unroll
    for (int c = 0; c < 3; ++c) {
        const float* p = p0 + c * HW;
        float v00 = __ldg(p + r0 + xc0);
        float v01 = __ldg(p + r0 + xc1);
        float v10 = __ldg(p + r1 + xc0);
        float v11 = __ldg(p + r1 + xc1);
        float s = fmaf(w00, v00, fmaf(w01, v01, fmaf(w10, v10, w11 * v11)));
        a0 = fmaf(c_dw[0 * 27 + c * 9 + k], s, a0);
        a1 = fmaf(c_dw[1 * 27 + c * 9 + k], s, a1);
        a2 = fmaf(c_dw[2 * 27 + c * 9 + k], s, a2);
    }
}

// One pass: conv for och [2*K0, 2*K0+2*NT) over 4 px, then sample taps [K0, K0+NT).
template<int K0, int NT>
__device__ __forceinline__ void pass(const float* __restrict__ s_x,
                                     int tx, int ty,
                                     const float* __restrict__ p0,
                                     int h, int wp,
                                     float* __restrict__ a0,
                                     float* __restrict__ a1,
                                     float* __restrict__ a2) {
    float acc[2 * NT][4];
#pragma unroll
    for (int j = 0; j < 2 * NT; ++j) {
        float bv = c_ob[2 * K0 + j];
#pragma unroll
        for (int px = 0; px < 4; ++px) acc[j][px] = bv;
    }

#pragma unroll
    for (int ci = 0; ci < CIN; ++ci) {
#pragma unroll
        for (int ky = 0; ky < 3; ++ky) {
            const float* rp = s_x + (ci * SHD + (ty + ky)) * SWD + 4 * tx;
            float4 qa = *reinterpret_cast<const float4*>(rp);      // v0..v3 (16B aligned)
            float2 qb = *reinterpret_cast<const float2*>(rp + 4);  // v4,v5
            float v[6] = {qa.x, qa.y, qa.z, qa.w, qb.x, qb.y};
#pragma unroll
            for (int j = 0; j < 2 * NT; ++j) {
                const int o = 2 * K0 + j;
                float w0 = c_ow[o * 72 + ci * 9 + ky * 3 + 0];
                float w1 = c_ow[o * 72 + ci * 9 + ky * 3 + 1];
                float w2 = c_ow[o * 72 + ci * 9 + ky * 3 + 2];
#pragma unroll
                for (int px = 0; px < 4; ++px)
                    acc[j][px] = fmaf(v[px], w0,
                                 fmaf(v[px + 1], w1,
                                 fmaf(v[px + 2], w2, acc[j][px])));
            }
        }
    }

#pragma unroll
    for (int t = 0; t < NT; ++t) {
        const int k   = K0 + t;
        const int kyi = k / 3, kxi = k % 3;
        const float by = (float)(kyi + h - 1);
#pragma unroll
        for (int px = 0; px < 4; ++px) {
            float py  = acc[2 * t][px]     + by;
            float pxx = acc[2 * t + 1][px] + (float)(kxi + wp + px - 1);
            sample_px(p0, py, pxx, k, a0[px], a1[px], a2[px]);
        }
    }
}

__global__ __launch_bounds__(256, 3)
void guided_cnn_fused(const float* __restrict__ pf,
                      const float* __restrict__ cf,
                      const float* __restrict__ mv,
                      float* __restrict__ out) {
    __shared__ float s_x[CIN * SHD * SWD];    // 42240 B

    const int tx  = threadIdx.x;              // 0..31 (4 px each)
    const int ty  = threadIdx.y;              // 0..7
    const int tid = ty * 32 + tx;
    const int b   = blockIdx.z;
    const int h0  = blockIdx.y * TH;
    const int w0  = blockIdx.x * TW;

    // stage input tile (8 ch, halo 1, rows padded to 132)
    for (int i = tid; i < CIN * SHD * SWD; i += 256) {
        int c  = i % SWD;
        int r  = (i / SWD) % SHD;
        int ch = i / (SWD * SHD);
        int gh = h0 - 1 + r;
        int gw = w0 - 1 + c;
        float v = 0.f;
        if (c < 130 && (unsigned)gh < (unsigned)HH && (unsigned)gw < (unsigned)WW) {
            const float* src;
            if (ch < 3)      src = pf + (((long)b * 3 + ch)     * HH + gh) * WW + gw;
            else if (ch < 6) src = cf + (((long)b * 3 + ch - 3) * HH + gh) * WW + gw;
            else             src = mv + (((long)b * 2 + ch - 6) * HH + gh) * WW + gw;
            v = __ldg(src);
        }
        s_x[i] = v;
    }
    __syncthreads();

    const int h  = h0 + ty;
    const int wp = w0 + 4 * tx;
    const float* p0 = pf + (long)b * 3 * HW;

    float a0[4] = {0, 0, 0, 0};
    float a1[4] = {0, 0, 0, 0};
    float a2[4] = {0, 0, 0, 0};

    pass<0, 3>(s_x, tx, ty, p0, h, wp, a0, a1, a2);   // och 0..5,  taps 0..2
    pass<3, 3>(s_x, tx, ty, p0, h, wp, a0, a1, a2);   // och 6..11, taps 3..5
    pass<6, 3>(s_x, tx, ty, p0, h, wp, a0, a1, a2);   // och 12..17, taps 6..8

    float* o0 = out + (((long)b * 3 + 0) * HH + h) * WW + wp;
    float* o1 = out + (((long)b * 3 + 1) * HH + h) * WW + wp;
    float* o2 = out + (((long)b * 3 + 2) * HH + h) * WW + wp;
    *reinterpret_cast<float4*>(o0) = make_float4(a0[0], a0[1], a0[2], a0[3]);
    *reinterpret_cast<float4*>(o1) = make_float4(a1[0], a1[1], a1[2], a1[3]);
    *reinterpret_cast<float4*>(o2) = make_float4(a2[0], a2[1], a2[2], a2[3]);
}

extern "C" void kernel_launch(void* const* d_in, const int* in_sizes, int n_in,
                              void* d_out, int out_size) {
    const float* pf = (const float*)d_in[0];
    const float* cf = (const float*)d_in[1];
    const float* mv = (const float*)d_in[2];
    const float* ow = (const float*)d_in[3];
    const float* ob = (const float*)d_in[4];
    const float* dw = (const float*)d_in[5];
    float* out = (float*)d_out;

    // Stage weights into __constant__ (async D2D memcpys are graph-capturable).
    cudaMemcpyToSymbolAsync(c_ow, ow, OCH * CIN * 9 * sizeof(float), 0,
                            cudaMemcpyDeviceToDevice, 0);
    cudaMemcpyToSymbolAsync(c_ob, ob, OCH * sizeof(float), 0,
                            cudaMemcpyDeviceToDevice, 0);
    cudaMemcpyToSymbolAsync(c_dw, dw, 81 * sizeof(float), 0,
                            cudaMemcpyDeviceToDevice, 0);

    dim3 blk(32, 8);
    dim3 grd(WW / TW, HH / TH, BB);   // 3 x 48 x 8 = 1152
    guided_cnn_fused<<<grd, blk>>>(pf, cf, mv, out);
}

// round 13
// speedup vs baseline: 2.9086x; 2.8098x over previous
#include <cuda_runtime.h>

#define BB   8
#define HH   384
#define WW   384
#define HW   (HH * WW)
#define CIN  8
#define OCH  18

// Weights in constant memory: reads use the constant port, not LDS/LDG.
__constant__ float c_ow[OCH * CIN * 9];   // [o][ci][ky*3+kx]
__constant__ float c_ob[OCH];
__constant__ float c_dw[81];              // [o][c][k] (3,3,9)

#define TW   128    // tile width  (32 threads x * 4 px)
#define TH   8      // tile height
#define SWD  132    // 130 used (128 + 2 halo), padded to 132 (16B rows)
#define SHD  10

// Bilinear sample of pf (3 ch, zero pad) + accumulate.
// EXACT R9 load pattern: predicated __ldg at one base + immediate offsets.
// Only change: floorf-based fract (saves the I2F per coordinate).
__device__ __forceinline__ void sample_px(const float* __restrict__ p0,
                                          float py, float px, int k,
                                          float& a0, float& a1, float& a2) {
    float fy = floorf(py);
    float fx = floorf(px);
    int y0 = (int)fy;                 // exact: fy is integral
    int x0 = (int)fx;
    float wy = py - fy;
    float wx = px - fx;
    bool y0v = ((unsigned)y0 < (unsigned)HH);
    bool y1v = ((unsigned)(y0 + 1) < (unsigned)HH);
    bool x0v = ((unsigned)x0 < (unsigned)WW);
    bool x1v = ((unsigned)(x0 + 1) < (unsigned)WW);
    float iy = 1.f - wy, ix = 1.f - wx;
    float w00 = iy * ix, w01 = iy * wx, w10 = wy * ix, w11 = wy * wx;
    int i00 = y0 * WW + x0;
#pragma unroll
    for (int c = 0; c < 3; ++c) {
        const float* p = p0 + c * HW;
        float v00 = (y0v && x0v) ? __ldg(p + i00)          : 0.f;
        float v01 = (y0v && x1v) ? __ldg(p + i00 + 1)      : 0.f;
        float v10 = (y1v && x0v) ? __ldg(p + i00 + WW)     : 0.f;
        float v11 = (y1v && x1v) ? __ldg(p + i00 + WW + 1) : 0.f;
        float s = fmaf(w00, v00, fmaf(w01, v01, fmaf(w10, v10, w11 * v11)));
        a0 = fmaf(c_dw[0 * 27 + c * 9 + k], s, a0);
        a1 = fmaf(c_dw[1 * 27 + c * 9 + k], s, a1);
        a2 = fmaf(c_dw[2 * 27 + c * 9 + k], s, a2);
    }
}

// One pass: conv for och [2*K0, 2*K0+2*NT) over 4 px, then sample taps [K0, K0+NT).
template<int K0, int NT>
__device__ __forceinline__ void pass(const float* __restrict__ s_x,
                                     int tx, int ty,
                                     const float* __restrict__ p0,
                                     int h, int wp,
                                     float* __restrict__ a0,
                                     float* __restrict__ a1,
                                     float* __restrict__ a2) {
    float acc[2 * NT][4];
#pragma unroll
    for (int j = 0; j < 2 * NT; ++j) {
        float bv = c_ob[2 * K0 + j];
#pragma unroll
        for (int px = 0; px < 4; ++px) acc[j][px] = bv;
    }

    // unroll 2 (not full): keeps SASS body I$-resident while leaving 6
    // (ci,ky) rows per iteration for ptxas load batching.
#pragma unroll 2
    for (int ci = 0; ci < CIN; ++ci) {
#pragma unroll
        for (int ky = 0; ky < 3; ++ky) {
            const float* rp = s_x + (ci * SHD + (ty + ky)) * SWD + 4 * tx;
            float4 qa = *reinterpret_cast<const float4*>(rp);      // v0..v3 (16B aligned)
            float2 qb = *reinterpret_cast<const float2*>(rp + 4);  // v4,v5
            float v[6] = {qa.x, qa.y, qa.z, qa.w, qb.x, qb.y};
#pragma unroll
            for (int j = 0; j < 2 * NT; ++j) {
                const int o = 2 * K0 + j;
                float w0 = c_ow[o * 72 + ci * 9 + ky * 3 + 0];
                float w1 = c_ow[o * 72 + ci * 9 + ky * 3 + 1];
                float w2 = c_ow[o * 72 + ci * 9 + ky * 3 + 2];
#pragma unroll
                for (int px = 0; px < 4; ++px)
                    acc[j][px] = fmaf(v[px], w0,
                                 fmaf(v[px + 1], w1,
                                 fmaf(v[px + 2], w2, acc[j][px])));
            }
        }
    }

#pragma unroll
    for (int t = 0; t < NT; ++t) {
        const int k   = K0 + t;
        const int kyi = k / 3, kxi = k % 3;
        const float by = (float)(kyi + h - 1);
#pragma unroll
        for (int px = 0; px < 4; ++px) {
            float py  = acc[2 * t][px]     + by;
            float pxx = acc[2 * t + 1][px] + (float)(kxi + wp + px - 1);
            sample_px(p0, py, pxx, k, a0[px], a1[px], a2[px]);
        }
    }
}

__global__ __launch_bounds__(256, 3)
void guided_cnn_fused(const float* __restrict__ pf,
                      const float* __restrict__ cf,
                      const float* __restrict__ mv,
                      float* __restrict__ out) {
    __shared__ float s_x[CIN * SHD * SWD];    // 42240 B

    const int tx  = threadIdx.x;              // 0..31 (4 px each)
    const int ty  = threadIdx.y;              // 0..7
    const int tid = ty * 32 + tx;
    const int b   = blockIdx.z;
    const int h0  = blockIdx.y * TH;
    const int w0  = blockIdx.x * TW;

    // stage input tile (8 ch, halo 1, rows padded to 132)
    for (int i = tid; i < CIN * SHD * SWD; i += 256) {
        int c  = i % SWD;
        int r  = (i / SWD) % SHD;
        int ch = i / (SWD * SHD);
        int gh = h0 - 1 + r;
        int gw = w0 - 1 + c;
        float v = 0.f;
        if (c < 130 && (unsigned)gh < (unsigned)HH && (unsigned)gw < (unsigned)WW) {
            const float* src;
            if (ch < 3)      src = pf + (((long)b * 3 + ch)     * HH + gh) * WW + gw;
            else if (ch < 6) src = cf + (((long)b * 3 + ch - 3) * HH + gh) * WW + gw;
            else             src = mv + (((long)b * 2 + ch - 6) * HH + gh) * WW + gw;
            v = __ldg(src);
        }
        s_x[i] = v;
    }
    __syncthreads();

    const int h  = h0 + ty;
    const int wp = w0 + 4 * tx;
    const float* p0 = pf + (long)b * 3 * HW;

    float a0[4] = {0, 0, 0, 0};
    float a1[4] = {0, 0, 0, 0};
    float a2[4] = {0, 0, 0, 0};

    pass<0, 3>(s_x, tx, ty, p0, h, wp, a0, a1, a2);   // och 0..5,  taps 0..2
    pass<3, 3>(s_x, tx, ty, p0, h, wp, a0, a1, a2);   // och 6..11, taps 3..5
    pass<6, 3>(s_x, tx, ty, p0, h, wp, a0, a1, a2);   // och 12..17, taps 6..8

    float* o0 = out + (((long)b * 3 + 0) * HH + h) * WW + wp;
    float* o1 = out + (((long)b * 3 + 1) * HH + h) * WW + wp;
    float* o2 = out + (((long)b * 3 + 2) * HH + h) * WW + wp;
    *reinterpret_cast<float4*>(o0) = make_float4(a0[0], a0[1], a0[2], a0[3]);
    *reinterpret_cast<float4*>(o1) = make_float4(a1[0], a1[1], a1[2], a1[3]);
    *reinterpret_cast<float4*>(o2) = make_float4(a2[0], a2[1], a2[2], a2[3]);
}

extern "C" void kernel_launch(void* const* d_in, const int* in_sizes, int n_in,
                              void* d_out, int out_size) {
    const float* pf = (const float*)d_in[0];
    const float* cf = (const float*)d_in[1];
    const float* mv = (const float*)d_in[2];
    const float* ow = (const float*)d_in[3];
    const float* ob = (const float*)d_in[4];
    const float* dw = (const float*)d_in[5];
    float* out = (float*)d_out;

    // Stage weights into __constant__ (async D2D memcpys are graph-capturable).
    cudaMemcpyToSymbolAsync(c_ow, ow, OCH * CIN * 9 * sizeof(float), 0,
                            cudaMemcpyDeviceToDevice, 0);
    cudaMemcpyToSymbolAsync(c_ob, ob, OCH * sizeof(float), 0,
                            cudaMemcpyDeviceToDevice, 0);
    cudaMemcpyToSymbolAsync(c_dw, dw, 81 * sizeof(float), 0,
                            cudaMemcpyDeviceToDevice, 0);

    dim3 blk(32, 8);
    dim3 grd(WW / TW, HH / TH, BB);   // 3 x 48 x 8 = 1152
    guided_cnn_fused<<<grd, blk>>>(pf, cf, mv, out);
}